// round 14
// baseline (speedup 1.0000x reference)
#include <cuda_runtime.h>
#include <cuda_fp16.h>
#include <stdint.h>

#define TPB        1024
#define NDMX       128                          // demux team: warps 0..3
#define NCONS      (TPB - NDMX)                 // 896 consumer threads: warps 4..31
#define CNT        8192
#define SPG        8192
#define CHUNK_PTS  128
#define NCHUNK     (CNT / CHUNK_PTS)            // 64 chunks per group
#define ARR_BYTES  (CHUNK_PTS * 9 * 4)          // 4608 B per array per chunk
#define RAW_SLOT_B (2 * ARR_BYTES)              // 9216 B per slot
#define NSLOT      3
#define BUF_B      (12 * CNT)                   // 98304 B per fp16 group buffer
#define RING_OFF   (2 * BUF_B)                  // 196608
#define MBAR_OFF   (RING_OFF + NSLOT * RAW_SLOT_B) // 224256
// mbar layout: full[s]=+8s (s<3), ready[b]=+24+8b, done[b]=+40+8b
#define SMEM_BYTES (MBAR_OFF + 64)              // 224320 B

__device__ double g_acc = 0.0;
__device__ unsigned int g_count = 0;

__device__ __forceinline__ uint32_t smem_u32(const void* p) {
    return (uint32_t)__cvta_generic_to_shared(p);
}
__device__ __forceinline__ void mbar_init(uint32_t mbar, uint32_t cnt) {
    asm volatile("mbarrier.init.shared.b64 [%0], %1;" :: "r"(mbar), "r"(cnt) : "memory");
}
__device__ __forceinline__ void mbar_arrive(uint32_t mbar) {
    asm volatile("mbarrier.arrive.release.cta.shared::cta.b64 _, [%0];" :: "r"(mbar) : "memory");
}
__device__ __forceinline__ void mbar_expect_tx(uint32_t mbar, uint32_t bytes) {
    asm volatile("mbarrier.arrive.expect_tx.shared.b64 _, [%0], %1;"
                 :: "r"(mbar), "r"(bytes) : "memory");
}
// NOTE: contains bra.uni -> must ALWAYS be executed warp-convergent.
__device__ __forceinline__ void mbar_wait(uint32_t mbar, uint32_t parity) {
    uint32_t done;
    asm volatile(
        "{\n\t.reg .pred p;\n\t"
        "mbarrier.try_wait.parity.acquire.cta.shared::cta.b64 p, [%1], %2;\n\t"
        "selp.b32 %0, 1, 0, p;\n\t}"
        : "=r"(done) : "r"(mbar), "r"(parity) : "memory");
    if (!done) {
        asm volatile(
            "{\n\t.reg .pred P1;\n\t"
            "W_%=:\n\t"
            "mbarrier.try_wait.parity.acquire.cta.shared::cta.b64 P1, [%0], %1, 0x989680;\n\t"
            "@P1 bra.uni D_%=;\n\t"
            "bra.uni W_%=;\n\t"
            "D_%=:\n\t}"
            :: "r"(mbar), "r"(parity) : "memory");
    }
}
__device__ __forceinline__ void bulk_copy(uint32_t dst, const void* src,
                                          uint32_t bytes, uint32_t mbar) {
    asm volatile(
        "cp.async.bulk.shared::cta.global.mbarrier::complete_tx::bytes [%0], [%1], %2, [%3];"
        :: "r"(dst), "l"(src), "r"(bytes), "r"(mbar) : "memory");
}
#define TEAM_BAR() asm volatile("bar.sync 2, %0;" :: "n"(NDMX) : "memory")

__device__ __forceinline__ float pair_term(int l, int r, const __half2* __restrict__ buf)
{
    float2 a  = __half22float2(buf[3 * l + 0]);   // in.xy
    float2 mz = __half22float2(buf[3 * l + 1]);   // (in.z, tg.z)
    float2 c  = __half22float2(buf[3 * l + 2]);   // tg.xy
    float2 b  = __half22float2(buf[3 * r + 0]);
    float2 nz = __half22float2(buf[3 * r + 1]);
    float2 d  = __half22float2(buf[3 * r + 2]);

    float ux = a.x - b.x, uy = a.y - b.y, uz = mz.x - nz.x;
    float d_in = sqrtf(fmaf(ux, ux, fmaf(uy, uy, uz * uz)));

    float vx = c.x - d.x, vy = c.y - d.y, vz = mz.y - nz.y;
    float d_tg = sqrtf(fmaf(vx, vx, fmaf(vy, vy, vz * vz)));

    float t = d_in - d_tg;
    return t * t;
}

__global__ void __launch_bounds__(TPB, 1)
rgn_dbuf_kernel(const float* __restrict__ inputs,
                const float* __restrict__ target,
                const int* __restrict__ left,
                const int* __restrict__ right,
                float* __restrict__ out,
                int npairs, int ngroups)
{
    extern __shared__ unsigned char smem[];
    unsigned char* ring = smem + RING_OFF;
    const uint32_t ring_u32 = smem_u32(ring);
    const uint32_t mb = smem_u32(smem + MBAR_OFF);
    // full[s] = mb+8s ; ready[b] = mb+24+8b ; done[b] = mb+40+8b

    const int K = (ngroups - blockIdx.x + gridDim.x - 1) / gridDim.x;
    const int total = K * NCHUNK;

    if (threadIdx.x == 0) {
        #pragma unroll
        for (int s = 0; s < NSLOT; s++) mbar_init(mb + 8 * s, 1);   // full: tx-completed
        mbar_init(mb + 24, NDMX);  mbar_init(mb + 32, NDMX);        // ready[0/1]
        mbar_init(mb + 40, NCONS); mbar_init(mb + 48, NCONS);       // done[0/1]
    }
    __syncthreads();

    float acc = 0.0f;
    const int wid  = threadIdx.x >> 5;
    const int lane = threadIdx.x & 31;

    if (wid < 4) {
        // ================= demux + producer team (warps 0..3) =================
        const int tt = threadIdx.x;   // 0..127

        // initial TMA issues: chunks 0..NSLOT-1 into fresh slots
        if (tt == 0) {
            #pragma unroll
            for (int ic = 0; ic < NSLOT; ic++) {
                if (ic < total) {
                    const int g  = blockIdx.x + (ic / NCHUNK) * gridDim.x;
                    const int ci = ic & (NCHUNK - 1);
                    const float* sin = inputs + (size_t)g * CNT * 9 + (size_t)ci * CHUNK_PTS * 9;
                    const float* stg = target + (size_t)g * CNT * 9 + (size_t)ci * CHUNK_PTS * 9;
                    const uint32_t slot = ring_u32 + (uint32_t)(ic % NSLOT) * RAW_SLOT_B;
                    mbar_expect_tx(mb + 8 * (ic % NSLOT), RAW_SLOT_B);
                    bulk_copy(slot, sin, ARR_BYTES, mb + 8 * (ic % NSLOT));
                    bulk_copy(slot + ARR_BYTES, stg, ARR_BYTES, mb + 8 * (ic % NSLOT));
                }
            }
        }

        for (int r = 0; r < K; r++) {
            const int b = r & 1;
            // before overwriting buf[b]: consumers must be done with group r-2
            if (r >= 2) mbar_wait(mb + 40 + 8 * b, (uint32_t)(((r >> 1) - 1) & 1));

            unsigned char* bufb = smem + (size_t)b * BUF_B;

            for (int ci = 0; ci < NCHUNK; ci++) {
                const int ic = r * NCHUNK + ci;
                const int s  = ic % NSLOT;
                mbar_wait(mb + 8 * s, (uint32_t)((ic / NSLOT) & 1));   // warp-convergent

                // demux: thread tt handles point row tt of both arrays
                const unsigned char* slot = ring + (size_t)s * RAW_SLOT_B;
                {
                    const float* ri = (const float*)(slot + 36 * tt + 12);
                    const float* rt = (const float*)(slot + ARR_BYTES + 36 * tt + 12);
                    float ix = ri[0], iy = ri[1], iz = ri[2];
                    float tx = rt[0], ty = rt[1], tz = rt[2];
                    const int p = ci * CHUNK_PTS + tt;
                    *(__half2*)(bufb + 12 * p + 0) = __floats2half2_rn(ix, iy);
                    *(__half2*)(bufb + 12 * p + 4) = __floats2half2_rn(iz, tz);
                    *(__half2*)(bufb + 12 * p + 8) = __floats2half2_rn(tx, ty);
                }
                TEAM_BAR();   // all team reads of slot s done -> safe to reissue

                if (tt == 0 && ic + NSLOT < total) {
                    const int jc = ic + NSLOT;          // reuses slot s
                    const int g2  = blockIdx.x + (jc / NCHUNK) * gridDim.x;
                    const int ci2 = jc & (NCHUNK - 1);
                    const float* sin = inputs + (size_t)g2 * CNT * 9 + (size_t)ci2 * CHUNK_PTS * 9;
                    const float* stg = target + (size_t)g2 * CNT * 9 + (size_t)ci2 * CHUNK_PTS * 9;
                    const uint32_t slot2 = ring_u32 + (uint32_t)s * RAW_SLOT_B;
                    mbar_expect_tx(mb + 8 * s, RAW_SLOT_B);
                    bulk_copy(slot2, sin, ARR_BYTES, mb + 8 * s);
                    bulk_copy(slot2 + ARR_BYTES, stg, ARR_BYTES, mb + 8 * s);
                }
            }
            // group r fully demuxed; publish to consumers (128 release-arrivals)
            mbar_arrive(mb + 24 + 8 * b);
        }
    } else {
        // ================= consumers (warps 4..31, 896 threads) =================
        const int ct = threadIdx.x - NDMX;   // 0..895

        for (int r = 0; r < K; r++) {
            const int b = r & 1;
            mbar_wait(mb + 24 + 8 * b, (uint32_t)((r >> 1) & 1));   // buf[b] ready

            const __half2* buf = (const __half2*)(smem + (size_t)b * BUF_B);
            const int g = blockIdx.x + r * gridDim.x;
            const int4* Lg = (const int4*)(left  + (size_t)g * SPG);
            const int4* Rg = (const int4*)(right + (size_t)g * SPG);
            for (int i = ct; i < SPG / 4; i += NCONS) {
                int4 L = __ldg(Lg + i);
                int4 R = __ldg(Rg + i);
                acc += pair_term(L.x & (CNT - 1), R.x & (CNT - 1), buf);
                acc += pair_term(L.y & (CNT - 1), R.y & (CNT - 1), buf);
                acc += pair_term(L.z & (CNT - 1), R.z & (CNT - 1), buf);
                acc += pair_term(L.w & (CNT - 1), R.w & (CNT - 1), buf);
            }
            mbar_arrive(mb + 40 + 8 * b);   // buf[b] consumed (896 arrivals)
        }
    }

    __syncthreads();   // converge all 1024 threads

    // block reduce
    #pragma unroll
    for (int off = 16; off > 0; off >>= 1)
        acc += __shfl_down_sync(0xFFFFFFFFu, acc, off);

    __shared__ float warp_sums[TPB / 32];
    if (lane == 0) warp_sums[wid] = acc;
    __syncthreads();

    if (wid == 0) {
        float s = (lane < TPB / 32) ? warp_sums[lane] : 0.0f;
        #pragma unroll
        for (int off = 16; off > 0; off >>= 1)
            s += __shfl_down_sync(0xFFFFFFFFu, s, off);

        if (lane == 0) {
            atomicAdd(&g_acc, (double)s);
            __threadfence();
            unsigned int done = atomicAdd(&g_count, 1u);
            if (done == gridDim.x - 1) {
                out[0] = (float)(g_acc / (double)npairs);
                g_acc = 0.0;     // reset for next graph replay
                g_count = 0;
            }
        }
    }
}

extern "C" void kernel_launch(void* const* d_in, const int* in_sizes, int n_in,
                              void* d_out, int out_size) {
    const float* inputs = (const float*)d_in[0];
    const float* target = (const float*)d_in[1];
    const int*   left   = (const int*)d_in[2];
    const int*   right  = (const int*)d_in[3];
    float* out = (float*)d_out;

    int npairs  = in_sizes[2];
    int ngroups = npairs / SPG;   // 512

    static int num_sms = 0;
    if (num_sms == 0) {
        cudaDeviceProp prop;
        cudaGetDeviceProperties(&prop, 0);
        num_sms = prop.multiProcessorCount;   // 152 on GB300
    }
    int grid = (num_sms < ngroups) ? num_sms : ngroups;

    cudaFuncSetAttribute(rgn_dbuf_kernel,
                         cudaFuncAttributeMaxDynamicSharedMemorySize, SMEM_BYTES);

    rgn_dbuf_kernel<<<grid, TPB, SMEM_BYTES>>>(inputs, target, left, right,
                                               out, npairs, ngroups);
}